// round 13
// baseline (speedup 1.0000x reference)
#include <cuda_runtime.h>
#include <cuda_bf16.h>
#include <cstdint>

static constexpr int Bb = 256;
static constexpr int Aa = 32;
static constexpr int Dd = 2048;

// ---------------- device scratch (allocation-free rule) ----------------
__device__ alignas(16) __nv_bfloat16 g_Ahi[Bb * Dd];
__device__ alignas(16) __nv_bfloat16 g_Alo[Bb * Dd];
__device__ alignas(16) __nv_bfloat16 g_Whi[Dd * Dd];   // [k][n] hi part
__device__ alignas(16) __nv_bfloat16 g_Wlo[Dd * Dd];   // [k][n] lo part
__device__ alignas(16) float g_part0[8][Bb * Dd];             // term0 fp32, per kz
__device__ alignas(16) __nv_bfloat16 g_partS[16][Bb * Dd];    // terms 1,2 bf16, per kz

// ---------------- PTX helpers (baseline sm_80+ features only) ----------
__device__ __forceinline__ uint32_t smem_u32(const void* p) {
    uint32_t a;
    asm("{ .reg .u64 t; cvta.to.shared.u64 t, %1; cvt.u32.u64 %0, t; }"
        : "=r"(a) : "l"(p));
    return a;
}
__device__ __forceinline__ void cp_async16(uint32_t dst, const void* src) {
    asm volatile("cp.async.cg.shared.global [%0], [%1], 16;"
                 :: "r"(dst), "l"(src) : "memory");
}
__device__ __forceinline__ void cp_commit() {
    asm volatile("cp.async.commit_group;" ::: "memory");
}
__device__ __forceinline__ void ldsm4(uint32_t& r0, uint32_t& r1, uint32_t& r2,
                                      uint32_t& r3, uint32_t addr) {
    asm volatile("ldmatrix.sync.aligned.m8n8.x4.shared.b16 {%0,%1,%2,%3}, [%4];"
                 : "=r"(r0), "=r"(r1), "=r"(r2), "=r"(r3) : "r"(addr));
}
__device__ __forceinline__ void ldsm4t(uint32_t& r0, uint32_t& r1, uint32_t& r2,
                                       uint32_t& r3, uint32_t addr) {
    asm volatile("ldmatrix.sync.aligned.m8n8.x4.trans.shared.b16 {%0,%1,%2,%3}, [%4];"
                 : "=r"(r0), "=r"(r1), "=r"(r2), "=r"(r3) : "r"(addr));
}
__device__ __forceinline__ void mma16816(float* d, const uint32_t* a,
                                         uint32_t b0, uint32_t b1) {
    asm volatile(
        "mma.sync.aligned.m16n8k16.row.col.f32.bf16.bf16.f32 "
        "{%0,%1,%2,%3}, {%4,%5,%6,%7}, {%8,%9}, {%0,%1,%2,%3};"
        : "+f"(d[0]), "+f"(d[1]), "+f"(d[2]), "+f"(d[3])
        : "r"(a[0]), "r"(a[1]), "r"(a[2]), "r"(a[3]), "r"(b0), "r"(b1));
}
__device__ __forceinline__ float4 ldcs4(const float4* p) {
    float4 v;
    asm volatile("ld.global.cs.v4.f32 {%0,%1,%2,%3}, [%4];"
                 : "=f"(v.x), "=f"(v.y), "=f"(v.z), "=f"(v.w) : "l"(p));
    return v;
}

// ---------------------------------------------------------------------------
// prep (R12-proven shape): blocks [0,512): masked agg -> A_hi/A_lo;
// blocks [512,1536): W fp32 -> bf16 hi/lo streaming convert.
// ---------------------------------------------------------------------------
static constexpr int AGG_BLKS = 512;
static constexpr int CVT_BLKS = 1024;

__global__ __launch_bounds__(256) void prep_kernel(
    const float* __restrict__ feat,
    const void* __restrict__ label_raw,
    const float* __restrict__ W)
{
    int bid = blockIdx.x;

    if (bid < AGG_BLKS) {
        __shared__ int s_idx[32];
        __shared__ int s_n;
        int b = bid >> 1;
        int half = bid & 1;

        if (threadIdx.x < 32) {
            // int64 labels (values 0/1) have all odd 32-bit words zero
            const int* l32 = (const int*)label_raw;
            int nz = 0;
            for (int i = threadIdx.x; i < 64; i += 32)
                if (l32[2 * i + 1] != 0) nz = 1;
            unsigned any = __ballot_sync(0xffffffffu, nz);
            int is_i64 = (any == 0u);

            int pred;
            if (is_i64) {
                const long long* l = (const long long*)label_raw;
                pred = (l[(size_t)b * Aa + threadIdx.x] > 0);
            } else {
                const int* l = (const int*)label_raw;
                pred = (l[(size_t)b * Aa + threadIdx.x] > 0);
            }
            unsigned m = __ballot_sync(0xffffffffu, pred);
            if (pred) s_idx[__popc(m & ((1u << threadIdx.x) - 1u))] = threadIdx.x;
            if (threadIdx.x == 0) s_n = __popc(m);
        }
        __syncthreads();
        int nact = s_n;

        const float4* f4 = reinterpret_cast<const float4*>(feat) + (size_t)b * Aa * (Dd / 4);
        __nv_bfloat162* hi2 = reinterpret_cast<__nv_bfloat162*>(g_Ahi + (size_t)b * Dd);
        __nv_bfloat162* lo2 = reinterpret_cast<__nv_bfloat162*>(g_Alo + (size_t)b * Dd);

        int i = half * 256 + threadIdx.x;
        float4 s = make_float4(0.f, 0.f, 0.f, 0.f);
#pragma unroll 4
        for (int j = 0; j < nact; j++) {
            float4 v = ldcs4(&f4[(size_t)s_idx[j] * (Dd / 4) + i]);
            s.x += v.x; s.y += v.y; s.z += v.z; s.w += v.w;
        }
        float vals[4] = {s.x, s.y, s.z, s.w};
        __nv_bfloat16 h[4], l[4];
#pragma unroll
        for (int j = 0; j < 4; j++) {
            h[j] = __float2bfloat16(vals[j]);
            l[j] = __float2bfloat16(vals[j] - __bfloat162float(h[j]));
        }
        hi2[i * 2 + 0] = __nv_bfloat162(h[0], h[1]);
        hi2[i * 2 + 1] = __nv_bfloat162(h[2], h[3]);
        lo2[i * 2 + 0] = __nv_bfloat162(l[0], l[1]);
        lo2[i * 2 + 1] = __nv_bfloat162(l[2], l[3]);
    } else {
        const float4* W4 = (const float4*)W;
        __nv_bfloat162* hi2 = (__nv_bfloat162*)g_Whi;
        __nv_bfloat162* lo2 = (__nv_bfloat162*)g_Wlo;
        int base = (bid - AGG_BLKS) * 1024 + threadIdx.x;

        float4 w[4];
#pragma unroll
        for (int u = 0; u < 4; u++) w[u] = ldcs4(&W4[base + u * 256]);

#pragma unroll
        for (int u = 0; u < 4; u++) {
            int i = base + u * 256;
            float vals[4] = {w[u].x, w[u].y, w[u].z, w[u].w};
            __nv_bfloat16 h[4], l[4];
#pragma unroll
            for (int j = 0; j < 4; j++) {
                h[j] = __float2bfloat16(vals[j]);
                l[j] = __float2bfloat16(vals[j] - __bfloat162float(h[j]));
            }
            hi2[i * 2 + 0] = __nv_bfloat162(h[0], h[1]);
            hi2[i * 2 + 1] = __nv_bfloat162(h[2], h[3]);
            lo2[i * 2 + 0] = __nv_bfloat162(l[0], l[1]);
            lo2[i * 2 + 1] = __nv_bfloat162(l[2], l[3]);
        }
    }
}

// ---------------------------------------------------------------------------
// bf16 GEMM via mma.sync. CTA tile 128(m) x 128(n), EIGHT-way K-split + 3
// terms across blockIdx.z (grid 16 x 2 x 24 = 768 CTAs, K=256 per CTA).
// 8 warps = 4(m) x 2(n); warp tile 32 x 64. 8 chunks of k32, 4-stage
// cp.async pipeline, one commit-group per iteration (empty commit in tail).
// term0 partials -> fp32 planes; small terms (1,2) -> bf16 planes.
// ---------------------------------------------------------------------------
static constexpr int STAGE_BYTES = 16384;    // A 8KB + B 2x4KB
static constexpr int NSTAGE = 4;
static constexpr int NCHUNK = 8;             // 256 / 32
static constexpr int GEMM_SMEM = NSTAGE * STAGE_BYTES;   // 64 KB dynamic

__global__ __launch_bounds__(256, 2) void gemm_kernel() {
    extern __shared__ __align__(128) char smbuf[];
    const uint32_t sbase = smem_u32(smbuf);

    const int tid = threadIdx.x;
    const int lane = tid & 31;
    const int wid = tid >> 5;
    const int wm = wid >> 1;          // warp m (0..3)
    const int wn = wid & 1;           // warp n half (0/1)

    const int n0 = blockIdx.x * 128;
    const int m0 = blockIdx.y * 128;
    const int zz = blockIdx.z;        // 0..23
    const int term = zz >> 3;         // 0: Ahi*Whi, 1: Ahi*Wlo, 2: Alo*Whi
    const int kz = zz & 7;
    const int kbase0 = kz * 256;

    const __nv_bfloat16* Ap = (term == 2) ? g_Alo : g_Ahi;
    const __nv_bfloat16* Bp = (term == 1) ? g_Wlo : g_Whi;
    const __nv_bfloat16* Ag = Ap + (size_t)m0 * Dd + kbase0;      // [m][k]
    const __nv_bfloat16* Bg = Bp + (size_t)kbase0 * Dd + n0;      // [k][n]

    const int g = lane >> 3;
    const int lr = lane & 7;

    // ldmatrix A offsets: rows 64B, swizzle c^((row>>1)&3). [mt][ks]
    uint32_t offA[2][2];
#pragma unroll
    for (int mt = 0; mt < 2; mt++) {
        int row = wm * 32 + mt * 16 + (g & 1) * 8 + lr;
#pragma unroll
        for (int ks = 0; ks < 2; ks++) {
            int c = 2 * ks + (g >> 1);
            offA[mt][ks] = row * 64 + ((c ^ ((row >> 1) & 3)) << 4);
        }
    }
    // ldmatrix B offsets (trans) within this warp's 4KB half: rows 128B,
    // swizzle c^(krow&7). [ks][q], q covers n16 each.
    const uint32_t bhalf = 8192 + wn * 4096;
    uint32_t offB[2][4];
#pragma unroll
    for (int ks = 0; ks < 2; ks++) {
        int krow = ks * 16 + (g & 1) * 8 + lr;
#pragma unroll
        for (int q = 0; q < 4; q++) {
            int c = 2 * q + (g >> 1);
            offB[ks][q] = bhalf + krow * 128 + ((c ^ (krow & 7)) << 4);
        }
    }

    // cp.async: A 8KB -> 2 chunks/thread; B 8KB -> 2 chunks/thread
    const int arow = tid >> 2, ac = tid & 3;
    const uint32_t aoff = arow * 64 + ((ac ^ ((arow >> 1) & 3)) << 4);
    const int brow = tid >> 3, bc = tid & 7;
    const uint32_t boff = brow * 128 + ((bc ^ (brow & 7)) << 4);

    auto issue_load = [&](int chunk) {
        int kt = chunk * 32;
        uint32_t st = sbase + (chunk & (NSTAGE - 1)) * STAGE_BYTES;
        cp_async16(st + aoff, Ag + (size_t)arow * Dd + kt + ac * 8);
        cp_async16(st + aoff + 4096, Ag + (size_t)(arow + 64) * Dd + kt + ac * 8);
        cp_async16(st + 8192 + boff, Bg + (size_t)(kt + brow) * Dd + bc * 8);
        cp_async16(st + 12288 + boff, Bg + (size_t)(kt + brow) * Dd + 64 + bc * 8);
        cp_commit();
    };

    float acc[2][8][4];
#pragma unroll
    for (int mt = 0; mt < 2; mt++)
#pragma unroll
        for (int nf = 0; nf < 8; nf++)
#pragma unroll
            for (int k = 0; k < 4; k++) acc[mt][nf][k] = 0.f;

    issue_load(0); issue_load(1); issue_load(2);

    for (int i = 0; i < NCHUNK; i++) {
        // chunk i's group was committed 3 iterations ago; with exactly one
        // commit per iteration, wait_group 2 guarantees stage i has landed.
        asm volatile("cp.async.wait_group 2;" ::: "memory");
        __syncthreads();
        if (i + 3 < NCHUNK) issue_load(i + 3);
        else cp_commit();                      // empty group keeps accounting exact

        uint32_t st = sbase + (i & (NSTAGE - 1)) * STAGE_BYTES;

#pragma unroll
        for (int ks = 0; ks < 2; ks++) {
            uint32_t a[2][4], b[4][4];
            ldsm4(a[0][0], a[0][1], a[0][2], a[0][3], st + offA[0][ks]);
            ldsm4(a[1][0], a[1][1], a[1][2], a[1][3], st + offA[1][ks]);
#pragma unroll
            for (int q = 0; q < 4; q++)
                ldsm4t(b[q][0], b[q][1], b[q][2], b[q][3], st + offB[ks][q]);

#pragma unroll
            for (int mt = 0; mt < 2; mt++)
#pragma unroll
                for (int q = 0; q < 4; q++) {
                    mma16816(acc[mt][2 * q + 0], a[mt], b[q][0], b[q][1]);
                    mma16816(acc[mt][2 * q + 1], a[mt], b[q][2], b[q][3]);
                }
        }
    }
    asm volatile("cp.async.wait_group 0;" ::: "memory");

    // epilogue: warp owns rows [wm*32, wm*32+32), cols [wn*64, wn*64+64)
    if (term == 0) {
        float* gp = g_part0[kz];
#pragma unroll
        for (int mt = 0; mt < 2; mt++)
#pragma unroll
            for (int nf = 0; nf < 8; nf++) {
                int grow = m0 + wm * 32 + mt * 16 + (lane >> 2);
                int gcol = n0 + wn * 64 + nf * 8 + (lane & 3) * 2;
                *(float2*)&gp[(size_t)grow * Dd + gcol] =
                    make_float2(acc[mt][nf][0], acc[mt][nf][1]);
                *(float2*)&gp[(size_t)(grow + 8) * Dd + gcol] =
                    make_float2(acc[mt][nf][2], acc[mt][nf][3]);
            }
    } else {
        __nv_bfloat16* gp = g_partS[(term - 1) * 8 + kz];
#pragma unroll
        for (int mt = 0; mt < 2; mt++)
#pragma unroll
            for (int nf = 0; nf < 8; nf++) {
                int grow = m0 + wm * 32 + mt * 16 + (lane >> 2);
                int gcol = n0 + wn * 64 + nf * 8 + (lane & 3) * 2;
                *(__nv_bfloat162*)&gp[(size_t)grow * Dd + gcol] =
                    __floats2bfloat162_rn(acc[mt][nf][0], acc[mt][nf][1]);
                *(__nv_bfloat162*)&gp[(size_t)(grow + 8) * Dd + gcol] =
                    __floats2bfloat162_rn(acc[mt][nf][2], acc[mt][nf][3]);
            }
    }
}

// ---------------------------------------------------------------------------
// finish: out = tanh(sum of 8 fp32 + 16 bf16 partial planes + bias)
// (fixed order -> deterministic)
// ---------------------------------------------------------------------------
__global__ __launch_bounds__(256) void finish_kernel(
    const float* __restrict__ bias, float* __restrict__ out)
{
    int idx = blockIdx.x * 256 + threadIdx.x;        // float4 index
    int n4 = idx & (Dd / 4 - 1);
    float4 s = make_float4(0.f, 0.f, 0.f, 0.f);
#pragma unroll
    for (int p = 0; p < 8; p++) {
        float4 v = ldcs4(((const float4*)g_part0[p]) + idx);
        s.x += v.x; s.y += v.y; s.z += v.z; s.w += v.w;
    }
#pragma unroll
    for (int p = 0; p < 16; p++) {
        const __nv_bfloat162* bp = (const __nv_bfloat162*)g_partS[p];
        float2 f0 = __bfloat1622float2(bp[idx * 2 + 0]);
        float2 f1 = __bfloat1622float2(bp[idx * 2 + 1]);
        s.x += f0.x; s.y += f0.y; s.z += f1.x; s.w += f1.y;
    }
    float4 bv = ((const float4*)bias)[n4];
    float4 r;
    r.x = tanhf(s.x + bv.x);
    r.y = tanhf(s.y + bv.y);
    r.z = tanhf(s.z + bv.z);
    r.w = tanhf(s.w + bv.w);
    ((float4*)out)[idx] = r;
}

// ---------------------------------------------------------------------------
// launch: inputs x, attribute_feat, attribute_label, W, b  (x unused: adj[A][A]=0)
// ---------------------------------------------------------------------------
extern "C" void kernel_launch(void* const* d_in, const int* in_sizes, int n_in,
                              void* d_out, int out_size) {
    (void)in_sizes; (void)n_in; (void)out_size;
    const float* feat  = (const float*)d_in[1];
    const void*  label = d_in[2];
    const float* W     = (const float*)d_in[3];
    const float* bias  = (const float*)d_in[4];
    float* out = (float*)d_out;

    cudaFuncSetAttribute(gemm_kernel, cudaFuncAttributeMaxDynamicSharedMemorySize, GEMM_SMEM);

    prep_kernel<<<AGG_BLKS + CVT_BLKS, 256>>>(feat, label, W);
    gemm_kernel<<<dim3(Dd / 128, Bb / 128, 24), 256, GEMM_SMEM>>>();
    finish_kernel<<<(Bb * Dd / 4) / 256, 256>>>(bias, out);
}

// round 16
// speedup vs baseline: 1.0642x; 1.0642x over previous
#include <cuda_runtime.h>
#include <cuda_bf16.h>
#include <cstdint>

static constexpr int Bb = 256;
static constexpr int Aa = 32;
static constexpr int Dd = 2048;

// ---------------- device scratch (allocation-free rule) ----------------
__device__ alignas(16) __nv_bfloat16 g_Ahi[Bb * Dd];
__device__ alignas(16) __nv_bfloat16 g_Alo[Bb * Dd];
__device__ alignas(16) float g_part[8][Bb * Dd];   // per-kz fp32 partials (terms fused)

// ---------------- PTX helpers (baseline sm_80+ features only) ----------
__device__ __forceinline__ uint32_t smem_u32(const void* p) {
    uint32_t a;
    asm("{ .reg .u64 t; cvta.to.shared.u64 t, %1; cvt.u32.u64 %0, t; }"
        : "=r"(a) : "l"(p));
    return a;
}
__device__ __forceinline__ void cp_async16(uint32_t dst, const void* src) {
    asm volatile("cp.async.cg.shared.global [%0], [%1], 16;"
                 :: "r"(dst), "l"(src) : "memory");
}
__device__ __forceinline__ void cp_commit() {
    asm volatile("cp.async.commit_group;" ::: "memory");
}
__device__ __forceinline__ void ldsm4(uint32_t& r0, uint32_t& r1, uint32_t& r2,
                                      uint32_t& r3, uint32_t addr) {
    asm volatile("ldmatrix.sync.aligned.m8n8.x4.shared.b16 {%0,%1,%2,%3}, [%4];"
                 : "=r"(r0), "=r"(r1), "=r"(r2), "=r"(r3) : "r"(addr));
}
__device__ __forceinline__ void ldsm4t(uint32_t& r0, uint32_t& r1, uint32_t& r2,
                                       uint32_t& r3, uint32_t addr) {
    asm volatile("ldmatrix.sync.aligned.m8n8.x4.trans.shared.b16 {%0,%1,%2,%3}, [%4];"
                 : "=r"(r0), "=r"(r1), "=r"(r2), "=r"(r3) : "r"(addr));
}
__device__ __forceinline__ void mma16816(float* d, const uint32_t* a,
                                         uint32_t b0, uint32_t b1) {
    asm volatile(
        "mma.sync.aligned.m16n8k16.row.col.f32.bf16.bf16.f32 "
        "{%0,%1,%2,%3}, {%4,%5,%6,%7}, {%8,%9}, {%0,%1,%2,%3};"
        : "+f"(d[0]), "+f"(d[1]), "+f"(d[2]), "+f"(d[3])
        : "r"(a[0]), "r"(a[1]), "r"(a[2]), "r"(a[3]), "r"(b0), "r"(b1));
}
__device__ __forceinline__ float4 ldcs4(const float4* p) {
    float4 v;
    asm volatile("ld.global.cs.v4.f32 {%0,%1,%2,%3}, [%4];"
                 : "=f"(v.x), "=f"(v.y), "=f"(v.z), "=f"(v.w) : "l"(p));
    return v;
}
__device__ __forceinline__ uint32_t pack_bf2(__nv_bfloat16 a, __nv_bfloat16 b) {
    __nv_bfloat162 t(a, b);
    return *reinterpret_cast<uint32_t*>(&t);
}
// split 8 fp32 -> uint4 of hi-bf16 pairs and uint4 of lo-bf16 pairs
__device__ __forceinline__ void split8(const float* v, uint4& hi, uint4& lo) {
    __nv_bfloat16 h[8], l[8];
#pragma unroll
    for (int j = 0; j < 8; j++) {
        h[j] = __float2bfloat16(v[j]);
        l[j] = __float2bfloat16(v[j] - __bfloat162float(h[j]));
    }
    hi = make_uint4(pack_bf2(h[0], h[1]), pack_bf2(h[2], h[3]),
                    pack_bf2(h[4], h[5]), pack_bf2(h[6], h[7]));
    lo = make_uint4(pack_bf2(l[0], l[1]), pack_bf2(l[2], l[3]),
                    pack_bf2(l[4], l[5]), pack_bf2(l[6], l[7]));
}

// ---------------------------------------------------------------------------
// prep: masked agg only -> A_hi/A_lo bf16 (2 blocks per sample, R12-proven).
// W is consumed fp32 directly by the gemm (converted in-kernel).
// ---------------------------------------------------------------------------
static constexpr int AGG_BLKS = 512;

__global__ __launch_bounds__(256) void prep_kernel(
    const float* __restrict__ feat,
    const void* __restrict__ label_raw)
{
    __shared__ int s_idx[32];
    __shared__ int s_n;
    int b = blockIdx.x >> 1;
    int half = blockIdx.x & 1;

    if (threadIdx.x < 32) {
        // int64 labels (values 0/1) have all odd 32-bit words zero
        const int* l32 = (const int*)label_raw;
        int nz = 0;
        for (int i = threadIdx.x; i < 64; i += 32)
            if (l32[2 * i + 1] != 0) nz = 1;
        unsigned any = __ballot_sync(0xffffffffu, nz);
        int is_i64 = (any == 0u);

        int pred;
        if (is_i64) {
            const long long* l = (const long long*)label_raw;
            pred = (l[(size_t)b * Aa + threadIdx.x] > 0);
        } else {
            const int* l = (const int*)label_raw;
            pred = (l[(size_t)b * Aa + threadIdx.x] > 0);
        }
        unsigned m = __ballot_sync(0xffffffffu, pred);
        if (pred) s_idx[__popc(m & ((1u << threadIdx.x) - 1u))] = threadIdx.x;
        if (threadIdx.x == 0) s_n = __popc(m);
    }
    __syncthreads();
    int nact = s_n;

    const float4* f4 = reinterpret_cast<const float4*>(feat) + (size_t)b * Aa * (Dd / 4);
    __nv_bfloat162* hi2 = reinterpret_cast<__nv_bfloat162*>(g_Ahi + (size_t)b * Dd);
    __nv_bfloat162* lo2 = reinterpret_cast<__nv_bfloat162*>(g_Alo + (size_t)b * Dd);

    int i = half * 256 + threadIdx.x;
    float4 s = make_float4(0.f, 0.f, 0.f, 0.f);
#pragma unroll 4
    for (int j = 0; j < nact; j++) {
        float4 v = ldcs4(&f4[(size_t)s_idx[j] * (Dd / 4) + i]);
        s.x += v.x; s.y += v.y; s.z += v.z; s.w += v.w;
    }
    float vals[4] = {s.x, s.y, s.z, s.w};
    __nv_bfloat16 h[4], l[4];
#pragma unroll
    for (int j = 0; j < 4; j++) {
        h[j] = __float2bfloat16(vals[j]);
        l[j] = __float2bfloat16(vals[j] - __bfloat162float(h[j]));
    }
    hi2[i * 2 + 0] = __nv_bfloat162(h[0], h[1]);
    hi2[i * 2 + 1] = __nv_bfloat162(h[2], h[3]);
    lo2[i * 2 + 0] = __nv_bfloat162(l[0], l[1]);
    lo2[i * 2 + 1] = __nv_bfloat162(l[2], l[3]);
}

// ---------------------------------------------------------------------------
// Fused 3-term bf16 GEMM via mma.sync, W converted fp32->bf16 hi/lo IN-KERNEL.
// CTA tile 128(m) x 128(n), 8-way kz over blockIdx.z (grid 16x2x8 = 256 CTAs,
// K=256/CTA, 8 chunks of k32). All 3 terms (Ahi*Whi + Ahi*Wlo + Alo*Whi)
// accumulate into ONE fp32 accumulator -> one partial plane per kz.
// SMEM stage (32KB): [Ahi 8K][Alo 8K][Whi 2x4K halves][Wlo 2x4K halves].
// 3 stages (96KB dyn), A via cp.async (prefetch-2, one commit/iter,
// wait_group 1); W via register staging (ld fp32 chunk i+1 interleaved with
// mma of chunk i, convert+STS between k16 phases).
// ---------------------------------------------------------------------------
static constexpr int STAGE_BYTES = 32768;
static constexpr int NSTAGE = 3;
static constexpr int KZ = 8;
static constexpr int NCHUNK = (Dd / KZ) / 32;            // 8
static constexpr int GEMM_SMEM = NSTAGE * STAGE_BYTES;   // 96 KB dynamic

__global__ __launch_bounds__(256, 2) void gemm_kernel(const float* __restrict__ W) {
    extern __shared__ __align__(128) char smbuf[];
    const uint32_t sbase = smem_u32(smbuf);

    const int tid = threadIdx.x;
    const int lane = tid & 31;
    const int wid = tid >> 5;
    const int wm = wid >> 1;          // warp m (0..3)
    const int wn = wid & 1;           // warp n half (0/1)

    const int n0 = blockIdx.x * 128;
    const int m0 = blockIdx.y * 128;
    const int kz = blockIdx.z;        // 0..7
    const int kbase0 = kz * (Dd / KZ);

    const __nv_bfloat16* Ahi_g = g_Ahi + (size_t)m0 * Dd + kbase0;
    const __nv_bfloat16* Alo_g = g_Alo + (size_t)m0 * Dd + kbase0;
    const float* Wg = W + (size_t)kbase0 * Dd + n0;       // [k][n] fp32

    const int g = lane >> 3;
    const int lr = lane & 7;

    // ldmatrix A offsets (rows 64B, swizzle c^((row>>1)&3)). [mt][ks]
    uint32_t offA[2][2];
#pragma unroll
    for (int mt = 0; mt < 2; mt++) {
        int row = wm * 32 + mt * 16 + (g & 1) * 8 + lr;
#pragma unroll
        for (int ks = 0; ks < 2; ks++) {
            int c = 2 * ks + (g >> 1);
            offA[mt][ks] = row * 64 + ((c ^ ((row >> 1) & 3)) << 4);
        }
    }
    // ldmatrix B offsets (trans), relative within a W plane (two 4KB halves,
    // 128B rows, swizzle c^(krow&7)). [ks][q]
    uint32_t offB[2][4];
#pragma unroll
    for (int ks = 0; ks < 2; ks++) {
        int krow = ks * 16 + (g & 1) * 8 + lr;
#pragma unroll
        for (int q = 0; q < 4; q++) {
            int c = 2 * q + (g >> 1);
            offB[ks][q] = wn * 4096 + krow * 128 + ((c ^ (krow & 7)) << 4);
        }
    }

    // cp.async A assignment (both planes): 2 rows per thread per plane
    const int arow = tid >> 2, ac = tid & 3;
    const uint32_t aoff = arow * 64 + ((ac ^ ((arow >> 1) & 3)) << 4);

    auto issue_load = [&](int chunk) {
        int kt = chunk * 32;
        uint32_t st = sbase + (chunk % NSTAGE) * STAGE_BYTES;
        cp_async16(st + aoff, Ahi_g + (size_t)arow * Dd + kt + ac * 8);
        cp_async16(st + aoff + 4096, Ahi_g + (size_t)(arow + 64) * Dd + kt + ac * 8);
        cp_async16(st + 8192 + aoff, Alo_g + (size_t)arow * Dd + kt + ac * 8);
        cp_async16(st + 12288 + aoff, Alo_g + (size_t)(arow + 64) * Dd + kt + ac * 8);
        cp_commit();
    };

    // W conversion mapping: thread handles k-row (tid>>3), 16 n-cols at (tid&7)*16
    const int wkrow = tid >> 3;           // 0..31
    const int wng = tid & 7;              // 0..7
    const int whalf = wng >> 2;           // which 64-col half
    const int wc0 = (wng & 3) * 2;        // first 16B chunk index in half
    // sts offsets (relative to stage base) for the two 8-float sub-chunks, hi plane
    uint32_t wsts[2];
#pragma unroll
    for (int c = 0; c < 2; c++)
        wsts[c] = 16384 + whalf * 4096 + wkrow * 128 + (((wc0 + c) ^ (wkrow & 7)) << 4);
    const float* wg_t = Wg + (size_t)wkrow * Dd + wng * 16;

    // convert 8 floats (sub-chunk c of 2) of W chunk j into stage
    auto w_sts8 = [&](int j, int c, const float4& f0, const float4& f1) {
        float vals[8] = {f0.x, f0.y, f0.z, f0.w, f1.x, f1.y, f1.z, f1.w};
        uint4 hi, lo;
        split8(vals, hi, lo);
        char* stc = smbuf + (j % NSTAGE) * STAGE_BYTES;
        *reinterpret_cast<uint4*>(stc + wsts[c]) = hi;
        *reinterpret_cast<uint4*>(stc + wsts[c] + 8192) = lo;
    };

    float acc[2][8][4];
#pragma unroll
    for (int mt = 0; mt < 2; mt++)
#pragma unroll
        for (int nf = 0; nf < 8; nf++)
#pragma unroll
            for (int k = 0; k < 4; k++) acc[mt][nf][k] = 0.f;

    // prologue: A chunks 0,1 in flight; W chunk 0 converted into stage 0
    issue_load(0);
    issue_load(1);
    {
        const float4* wp = (const float4*)(wg_t);
        float4 f0 = wp[0], f1 = wp[1], f2 = wp[2], f3 = wp[3];
        w_sts8(0, 0, f0, f1);
        w_sts8(0, 1, f2, f3);
    }

    for (int i = 0; i < NCHUNK; i++) {
        // one commit per iteration; chunk i committed 2 iterations ago ->
        // wait_group 1 (only the newest group may pend) covers it.
        asm volatile("cp.async.wait_group 1;" ::: "memory");
        __syncthreads();
        if (i + 2 < NCHUNK) issue_load(i + 2);
        else cp_commit();                      // empty group keeps accounting exact

        const bool wvalid = (i + 1) < NCHUNK;
        const float4* wp = (const float4*)(wg_t + (size_t)(i + 1) * 32 * Dd);
        float4 f0, f1;
        if (wvalid) { f0 = wp[0]; f1 = wp[1]; }   // issue loads early

        uint32_t st = sbase + (i % NSTAGE) * STAGE_BYTES;

        // ---- k16 phase 0 ----
        {
            uint32_t ah[2][4], al[2][4], b[4][4];
            ldsm4(ah[0][0], ah[0][1], ah[0][2], ah[0][3], st + offA[0][0]);
            ldsm4(ah[1][0], ah[1][1], ah[1][2], ah[1][3], st + offA[1][0]);
            ldsm4(al[0][0], al[0][1], al[0][2], al[0][3], st + 8192 + offA[0][0]);
            ldsm4(al[1][0], al[1][1], al[1][2], al[1][3], st + 8192 + offA[1][0]);
#pragma unroll
            for (int q = 0; q < 4; q++)
                ldsm4t(b[q][0], b[q][1], b[q][2], b[q][3], st + 16384 + offB[0][q]);
#pragma unroll
            for (int mt = 0; mt < 2; mt++)
#pragma unroll
                for (int q = 0; q < 4; q++) {
                    mma16816(acc[mt][2 * q + 0], ah[mt], b[q][0], b[q][1]);
                    mma16816(acc[mt][2 * q + 1], ah[mt], b[q][2], b[q][3]);
                    mma16816(acc[mt][2 * q + 0], al[mt], b[q][0], b[q][1]);
                    mma16816(acc[mt][2 * q + 1], al[mt], b[q][2], b[q][3]);
                }
            // W-lo fragments reuse b regs
#pragma unroll
            for (int q = 0; q < 4; q++)
                ldsm4t(b[q][0], b[q][1], b[q][2], b[q][3], st + 24576 + offB[0][q]);
#pragma unroll
            for (int mt = 0; mt < 2; mt++)
#pragma unroll
                for (int q = 0; q < 4; q++) {
                    mma16816(acc[mt][2 * q + 0], ah[mt], b[q][0], b[q][1]);
                    mma16816(acc[mt][2 * q + 1], ah[mt], b[q][2], b[q][3]);
                }
        }

        float4 f2, f3;
        if (wvalid) {
            w_sts8(i + 1, 0, f0, f1);
            f2 = wp[2]; f3 = wp[3];
        }

        // ---- k16 phase 1 ----
        {
            uint32_t ah[2][4], al[2][4], b[4][4];
            ldsm4(ah[0][0], ah[0][1], ah[0][2], ah[0][3], st + offA[0][1]);
            ldsm4(ah[1][0], ah[1][1], ah[1][2], ah[1][3], st + offA[1][1]);
            ldsm4(al[0][0], al[0][1], al[0][2], al[0][3], st + 8192 + offA[0][1]);
            ldsm4(al[1][0], al[1][1], al[1][2], al[1][3], st + 8192 + offA[1][1]);
#pragma unroll
            for (int q = 0; q < 4; q++)
                ldsm4t(b[q][0], b[q][1], b[q][2], b[q][3], st + 16384 + offB[1][q]);
#pragma unroll
            for (int mt = 0; mt < 2; mt++)
#pragma unroll
                for (int q = 0; q < 4; q++) {
                    mma16816(acc[mt][2 * q + 0], ah[mt], b[q][0], b[q][1]);
                    mma16816(acc[mt][2 * q + 1], ah[mt], b[q][2], b[q][3]);
                    mma16816(acc[mt][2 * q + 0], al[mt], b[q][0], b[q][1]);
                    mma16816(acc[mt][2 * q + 1], al[mt], b[q][2], b[q][3]);
                }
#pragma unroll
            for (int q = 0; q < 4; q++)
                ldsm4t(b[q][0], b[q][1], b[q][2], b[q][3], st + 24576 + offB[1][q]);
#pragma unroll
            for (int mt = 0; mt < 2; mt++)
#pragma unroll
                for (int q = 0; q < 4; q++) {
                    mma16816(acc[mt][2 * q + 0], ah[mt], b[q][0], b[q][1]);
                    mma16816(acc[mt][2 * q + 1], ah[mt], b[q][2], b[q][3]);
                }
        }

        if (wvalid) w_sts8(i + 1, 1, f2, f3);
    }
    asm volatile("cp.async.wait_group 0;" ::: "memory");

    // epilogue: warp owns rows [wm*32, +32), cols [wn*64, +64)
    float* gp = g_part[kz];
#pragma unroll
    for (int mt = 0; mt < 2; mt++)
#pragma unroll
        for (int nf = 0; nf < 8; nf++) {
            int grow = m0 + wm * 32 + mt * 16 + (lane >> 2);
            int gcol = n0 + wn * 64 + nf * 8 + (lane & 3) * 2;
            *(float2*)&gp[(size_t)grow * Dd + gcol] =
                make_float2(acc[mt][nf][0], acc[mt][nf][1]);
            *(float2*)&gp[(size_t)(grow + 8) * Dd + gcol] =
                make_float2(acc[mt][nf][2], acc[mt][nf][3]);
        }
}

// ---------------------------------------------------------------------------
// finish: out = tanh(sum of 8 fp32 partial planes + bias)  (fixed order)
// ---------------------------------------------------------------------------
__global__ __launch_bounds__(256) void finish_kernel(
    const float* __restrict__ bias, float* __restrict__ out)
{
    int idx = blockIdx.x * 256 + threadIdx.x;        // float4 index
    int n4 = idx & (Dd / 4 - 1);
    float4 s = make_float4(0.f, 0.f, 0.f, 0.f);
#pragma unroll
    for (int p = 0; p < 8; p++) {
        float4 v = ldcs4(((const float4*)g_part[p]) + idx);
        s.x += v.x; s.y += v.y; s.z += v.z; s.w += v.w;
    }
    float4 bv = ((const float4*)bias)[n4];
    float4 r;
    r.x = tanhf(s.x + bv.x);
    r.y = tanhf(s.y + bv.y);
    r.z = tanhf(s.z + bv.z);
    r.w = tanhf(s.w + bv.w);
    ((float4*)out)[idx] = r;
}

// ---------------------------------------------------------------------------
// launch: inputs x, attribute_feat, attribute_label, W, b  (x unused: adj[A][A]=0)
// ---------------------------------------------------------------------------
extern "C" void kernel_launch(void* const* d_in, const int* in_sizes, int n_in,
                              void* d_out, int out_size) {
    (void)in_sizes; (void)n_in; (void)out_size;
    const float* feat  = (const float*)d_in[1];
    const void*  label = d_in[2];
    const float* W     = (const float*)d_in[3];
    const float* bias  = (const float*)d_in[4];
    float* out = (float*)d_out;

    cudaFuncSetAttribute(gemm_kernel, cudaFuncAttributeMaxDynamicSharedMemorySize, GEMM_SMEM);

    prep_kernel<<<AGG_BLKS, 256>>>(feat, label);
    gemm_kernel<<<dim3(Dd / 128, Bb / 128, KZ), 256, GEMM_SMEM>>>(W);
    finish_kernel<<<(Bb * Dd / 4) / 256, 256>>>(bias, out);
}

// round 17
// speedup vs baseline: 1.1566x; 1.0868x over previous
#include <cuda_runtime.h>
#include <cuda_bf16.h>
#include <cstdint>

static constexpr int Bb = 256;
static constexpr int Aa = 32;
static constexpr int Dd = 2048;

// ---------------- device scratch (allocation-free rule) ----------------
__device__ alignas(16) __nv_bfloat16 g_Ahi[Bb * Dd];
__device__ alignas(16) __nv_bfloat16 g_Alo[Bb * Dd];
__device__ alignas(16) float g_part[8][Bb * Dd];   // per-kz fp32 partials (terms fused)

// ---------------- PTX helpers (baseline sm_80+ features only) ----------
__device__ __forceinline__ uint32_t smem_u32(const void* p) {
    uint32_t a;
    asm("{ .reg .u64 t; cvta.to.shared.u64 t, %1; cvt.u32.u64 %0, t; }"
        : "=r"(a) : "l"(p));
    return a;
}
__device__ __forceinline__ void cp_async16(uint32_t dst, const void* src) {
    asm volatile("cp.async.cg.shared.global [%0], [%1], 16;"
                 :: "r"(dst), "l"(src) : "memory");
}
__device__ __forceinline__ void cp_commit() {
    asm volatile("cp.async.commit_group;" ::: "memory");
}
__device__ __forceinline__ void ldsm4(uint32_t& r0, uint32_t& r1, uint32_t& r2,
                                      uint32_t& r3, uint32_t addr) {
    asm volatile("ldmatrix.sync.aligned.m8n8.x4.shared.b16 {%0,%1,%2,%3}, [%4];"
                 : "=r"(r0), "=r"(r1), "=r"(r2), "=r"(r3) : "r"(addr));
}
__device__ __forceinline__ void ldsm4t(uint32_t& r0, uint32_t& r1, uint32_t& r2,
                                       uint32_t& r3, uint32_t addr) {
    asm volatile("ldmatrix.sync.aligned.m8n8.x4.trans.shared.b16 {%0,%1,%2,%3}, [%4];"
                 : "=r"(r0), "=r"(r1), "=r"(r2), "=r"(r3) : "r"(addr));
}
__device__ __forceinline__ void mma16816(float* d, const uint32_t* a,
                                         uint32_t b0, uint32_t b1) {
    asm volatile(
        "mma.sync.aligned.m16n8k16.row.col.f32.bf16.bf16.f32 "
        "{%0,%1,%2,%3}, {%4,%5,%6,%7}, {%8,%9}, {%0,%1,%2,%3};"
        : "+f"(d[0]), "+f"(d[1]), "+f"(d[2]), "+f"(d[3])
        : "r"(a[0]), "r"(a[1]), "r"(a[2]), "r"(a[3]), "r"(b0), "r"(b1));
}
__device__ __forceinline__ float4 ldcs4(const float4* p) {
    float4 v;
    asm volatile("ld.global.cs.v4.f32 {%0,%1,%2,%3}, [%4];"
                 : "=f"(v.x), "=f"(v.y), "=f"(v.z), "=f"(v.w) : "l"(p));
    return v;
}
__device__ __forceinline__ uint32_t pack_bf2(__nv_bfloat16 a, __nv_bfloat16 b) {
    __nv_bfloat162 t(a, b);
    return *reinterpret_cast<uint32_t*>(&t);
}
// split 8 fp32 -> uint4 of hi-bf16 pairs and uint4 of lo-bf16 pairs
__device__ __forceinline__ void split8(const float* v, uint4& hi, uint4& lo) {
    __nv_bfloat16 h[8], l[8];
#pragma unroll
    for (int j = 0; j < 8; j++) {
        h[j] = __float2bfloat16(v[j]);
        l[j] = __float2bfloat16(v[j] - __bfloat162float(h[j]));
    }
    hi = make_uint4(pack_bf2(h[0], h[1]), pack_bf2(h[2], h[3]),
                    pack_bf2(h[4], h[5]), pack_bf2(h[6], h[7]));
    lo = make_uint4(pack_bf2(l[0], l[1]), pack_bf2(l[2], l[3]),
                    pack_bf2(l[4], l[5]), pack_bf2(l[6], l[7]));
}

// ---------------------------------------------------------------------------
// prep: masked agg only -> A_hi/A_lo bf16 (2 blocks per sample, R12-proven).
// W is consumed fp32 directly by the gemm (converted in-kernel).
// ---------------------------------------------------------------------------
static constexpr int AGG_BLKS = 512;

__global__ __launch_bounds__(256) void prep_kernel(
    const float* __restrict__ feat,
    const void* __restrict__ label_raw)
{
    __shared__ int s_idx[32];
    __shared__ int s_n;
    int b = blockIdx.x >> 1;
    int half = blockIdx.x & 1;

    if (threadIdx.x < 32) {
        // int64 labels (values 0/1) have all odd 32-bit words zero
        const int* l32 = (const int*)label_raw;
        int nz = 0;
        for (int i = threadIdx.x; i < 64; i += 32)
            if (l32[2 * i + 1] != 0) nz = 1;
        unsigned any = __ballot_sync(0xffffffffu, nz);
        int is_i64 = (any == 0u);

        int pred;
        if (is_i64) {
            const long long* l = (const long long*)label_raw;
            pred = (l[(size_t)b * Aa + threadIdx.x] > 0);
        } else {
            const int* l = (const int*)label_raw;
            pred = (l[(size_t)b * Aa + threadIdx.x] > 0);
        }
        unsigned m = __ballot_sync(0xffffffffu, pred);
        if (pred) s_idx[__popc(m & ((1u << threadIdx.x) - 1u))] = threadIdx.x;
        if (threadIdx.x == 0) s_n = __popc(m);
    }
    __syncthreads();
    int nact = s_n;

    const float4* f4 = reinterpret_cast<const float4*>(feat) + (size_t)b * Aa * (Dd / 4);
    __nv_bfloat162* hi2 = reinterpret_cast<__nv_bfloat162*>(g_Ahi + (size_t)b * Dd);
    __nv_bfloat162* lo2 = reinterpret_cast<__nv_bfloat162*>(g_Alo + (size_t)b * Dd);

    int i = half * 256 + threadIdx.x;
    float4 s = make_float4(0.f, 0.f, 0.f, 0.f);
#pragma unroll 4
    for (int j = 0; j < nact; j++) {
        float4 v = ldcs4(&f4[(size_t)s_idx[j] * (Dd / 4) + i]);
        s.x += v.x; s.y += v.y; s.z += v.z; s.w += v.w;
    }
    float vals[4] = {s.x, s.y, s.z, s.w};
    __nv_bfloat16 h[4], l[4];
#pragma unroll
    for (int j = 0; j < 4; j++) {
        h[j] = __float2bfloat16(vals[j]);
        l[j] = __float2bfloat16(vals[j] - __bfloat162float(h[j]));
    }
    hi2[i * 2 + 0] = __nv_bfloat162(h[0], h[1]);
    hi2[i * 2 + 1] = __nv_bfloat162(h[2], h[3]);
    lo2[i * 2 + 0] = __nv_bfloat162(l[0], l[1]);
    lo2[i * 2 + 1] = __nv_bfloat162(l[2], l[3]);
}

// ---------------------------------------------------------------------------
// Fused 3-term bf16 GEMM via mma.sync, W converted fp32->bf16 hi/lo IN-KERNEL.
// CTA tile 128(m) x 128(n), 8-way kz over blockIdx.z (grid 16x2x8 = 256 CTAs,
// K=256/CTA, 8 chunks of k32). All 3 terms (Ahi*Whi + Ahi*Wlo + Alo*Whi)
// accumulate into ONE fp32 accumulator -> one partial plane per kz.
// SMEM stage (32KB): [Ahi 8K][Alo 8K][Whi 2x4K halves][Wlo 2x4K halves].
// 3 stages (96KB dyn), A via cp.async (prefetch-2, one commit/iter,
// wait_group 1); W via register staging (ld fp32 chunk i+1 interleaved with
// mma of chunk i, convert+STS between k16 phases).
// ---------------------------------------------------------------------------
static constexpr int STAGE_BYTES = 32768;
static constexpr int NSTAGE = 3;
static constexpr int KZ = 8;
static constexpr int NCHUNK = (Dd / KZ) / 32;            // 8
static constexpr int GEMM_SMEM = NSTAGE * STAGE_BYTES;   // 96 KB dynamic

__global__ __launch_bounds__(256, 2) void gemm_kernel(const float* __restrict__ W) {
    extern __shared__ __align__(128) char smbuf[];
    const uint32_t sbase = smem_u32(smbuf);

    const int tid = threadIdx.x;
    const int lane = tid & 31;
    const int wid = tid >> 5;
    const int wm = wid >> 1;          // warp m (0..3)
    const int wn = wid & 1;           // warp n half (0/1)

    const int n0 = blockIdx.x * 128;
    const int m0 = blockIdx.y * 128;
    const int kz = blockIdx.z;        // 0..7
    const int kbase0 = kz * (Dd / KZ);

    const __nv_bfloat16* Ahi_g = g_Ahi + (size_t)m0 * Dd + kbase0;
    const __nv_bfloat16* Alo_g = g_Alo + (size_t)m0 * Dd + kbase0;
    const float* Wg = W + (size_t)kbase0 * Dd + n0;       // [k][n] fp32

    const int g = lane >> 3;
    const int lr = lane & 7;

    // ldmatrix A offsets (rows 64B, swizzle c^((row>>1)&3)). [mt][ks]
    uint32_t offA[2][2];
#pragma unroll
    for (int mt = 0; mt < 2; mt++) {
        int row = wm * 32 + mt * 16 + (g & 1) * 8 + lr;
#pragma unroll
        for (int ks = 0; ks < 2; ks++) {
            int c = 2 * ks + (g >> 1);
            offA[mt][ks] = row * 64 + ((c ^ ((row >> 1) & 3)) << 4);
        }
    }
    // ldmatrix B offsets (trans), relative within a W plane (two 4KB halves,
    // 128B rows, swizzle c^(krow&7)). [ks][q]
    uint32_t offB[2][4];
#pragma unroll
    for (int ks = 0; ks < 2; ks++) {
        int krow = ks * 16 + (g & 1) * 8 + lr;
#pragma unroll
        for (int q = 0; q < 4; q++) {
            int c = 2 * q + (g >> 1);
            offB[ks][q] = wn * 4096 + krow * 128 + ((c ^ (krow & 7)) << 4);
        }
    }

    // cp.async A assignment (both planes): 2 rows per thread per plane
    const int arow = tid >> 2, ac = tid & 3;
    const uint32_t aoff = arow * 64 + ((ac ^ ((arow >> 1) & 3)) << 4);

    auto issue_load = [&](int chunk) {
        int kt = chunk * 32;
        uint32_t st = sbase + (chunk % NSTAGE) * STAGE_BYTES;
        cp_async16(st + aoff, Ahi_g + (size_t)arow * Dd + kt + ac * 8);
        cp_async16(st + aoff + 4096, Ahi_g + (size_t)(arow + 64) * Dd + kt + ac * 8);
        cp_async16(st + 8192 + aoff, Alo_g + (size_t)arow * Dd + kt + ac * 8);
        cp_async16(st + 12288 + aoff, Alo_g + (size_t)(arow + 64) * Dd + kt + ac * 8);
        cp_commit();
    };

    // W conversion mapping: thread handles k-row (tid>>3), 16 n-cols at (tid&7)*16
    const int wkrow = tid >> 3;           // 0..31
    const int wng = tid & 7;              // 0..7
    const int whalf = wng >> 2;           // which 64-col half
    const int wc0 = (wng & 3) * 2;        // first 16B chunk index in half
    // sts offsets (relative to stage base) for the two 8-float sub-chunks, hi plane
    uint32_t wsts[2];
#pragma unroll
    for (int c = 0; c < 2; c++)
        wsts[c] = 16384 + whalf * 4096 + wkrow * 128 + (((wc0 + c) ^ (wkrow & 7)) << 4);
    const float* wg_t = Wg + (size_t)wkrow * Dd + wng * 16;

    // convert 8 floats (sub-chunk c of 2) of W chunk j into stage
    auto w_sts8 = [&](int j, int c, const float4& f0, const float4& f1) {
        float vals[8] = {f0.x, f0.y, f0.z, f0.w, f1.x, f1.y, f1.z, f1.w};
        uint4 hi, lo;
        split8(vals, hi, lo);
        char* stc = smbuf + (j % NSTAGE) * STAGE_BYTES;
        *reinterpret_cast<uint4*>(stc + wsts[c]) = hi;
        *reinterpret_cast<uint4*>(stc + wsts[c] + 8192) = lo;
    };

    float acc[2][8][4];
#pragma unroll
    for (int mt = 0; mt < 2; mt++)
#pragma unroll
        for (int nf = 0; nf < 8; nf++)
#pragma unroll
            for (int k = 0; k < 4; k++) acc[mt][nf][k] = 0.f;

    // prologue: A chunks 0,1 in flight; W chunk 0 converted into stage 0
    issue_load(0);
    issue_load(1);
    {
        const float4* wp = (const float4*)(wg_t);
        float4 f0 = wp[0], f1 = wp[1], f2 = wp[2], f3 = wp[3];
        w_sts8(0, 0, f0, f1);
        w_sts8(0, 1, f2, f3);
    }

    for (int i = 0; i < NCHUNK; i++) {
        // one commit per iteration; chunk i committed 2 iterations ago ->
        // wait_group 1 (only the newest group may pend) covers it.
        asm volatile("cp.async.wait_group 1;" ::: "memory");
        __syncthreads();
        if (i + 2 < NCHUNK) issue_load(i + 2);
        else cp_commit();                      // empty group keeps accounting exact

        const bool wvalid = (i + 1) < NCHUNK;
        const float4* wp = (const float4*)(wg_t + (size_t)(i + 1) * 32 * Dd);
        float4 f0, f1;
        if (wvalid) { f0 = wp[0]; f1 = wp[1]; }   // issue loads early

        uint32_t st = sbase + (i % NSTAGE) * STAGE_BYTES;

        // ---- k16 phase 0 ----
        {
            uint32_t ah[2][4], al[2][4], b[4][4];
            ldsm4(ah[0][0], ah[0][1], ah[0][2], ah[0][3], st + offA[0][0]);
            ldsm4(ah[1][0], ah[1][1], ah[1][2], ah[1][3], st + offA[1][0]);
            ldsm4(al[0][0], al[0][1], al[0][2], al[0][3], st + 8192 + offA[0][0]);
            ldsm4(al[1][0], al[1][1], al[1][2], al[1][3], st + 8192 + offA[1][0]);
#pragma unroll
            for (int q = 0; q < 4; q++)
                ldsm4t(b[q][0], b[q][1], b[q][2], b[q][3], st + 16384 + offB[0][q]);
#pragma unroll
            for (int mt = 0; mt < 2; mt++)
#pragma unroll
                for (int q = 0; q < 4; q++) {
                    mma16816(acc[mt][2 * q + 0], ah[mt], b[q][0], b[q][1]);
                    mma16816(acc[mt][2 * q + 1], ah[mt], b[q][2], b[q][3]);
                    mma16816(acc[mt][2 * q + 0], al[mt], b[q][0], b[q][1]);
                    mma16816(acc[mt][2 * q + 1], al[mt], b[q][2], b[q][3]);
                }
            // W-lo fragments reuse b regs
#pragma unroll
            for (int q = 0; q < 4; q++)
                ldsm4t(b[q][0], b[q][1], b[q][2], b[q][3], st + 24576 + offB[0][q]);
#pragma unroll
            for (int mt = 0; mt < 2; mt++)
#pragma unroll
                for (int q = 0; q < 4; q++) {
                    mma16816(acc[mt][2 * q + 0], ah[mt], b[q][0], b[q][1]);
                    mma16816(acc[mt][2 * q + 1], ah[mt], b[q][2], b[q][3]);
                }
        }

        float4 f2, f3;
        if (wvalid) {
            w_sts8(i + 1, 0, f0, f1);
            f2 = wp[2]; f3 = wp[3];
        }

        // ---- k16 phase 1 ----
        {
            uint32_t ah[2][4], al[2][4], b[4][4];
            ldsm4(ah[0][0], ah[0][1], ah[0][2], ah[0][3], st + offA[0][1]);
            ldsm4(ah[1][0], ah[1][1], ah[1][2], ah[1][3], st + offA[1][1]);
            ldsm4(al[0][0], al[0][1], al[0][2], al[0][3], st + 8192 + offA[0][1]);
            ldsm4(al[1][0], al[1][1], al[1][2], al[1][3], st + 8192 + offA[1][1]);
#pragma unroll
            for (int q = 0; q < 4; q++)
                ldsm4t(b[q][0], b[q][1], b[q][2], b[q][3], st + 16384 + offB[1][q]);
#pragma unroll
            for (int mt = 0; mt < 2; mt++)
#pragma unroll
                for (int q = 0; q < 4; q++) {
                    mma16816(acc[mt][2 * q + 0], ah[mt], b[q][0], b[q][1]);
                    mma16816(acc[mt][2 * q + 1], ah[mt], b[q][2], b[q][3]);
                    mma16816(acc[mt][2 * q + 0], al[mt], b[q][0], b[q][1]);
                    mma16816(acc[mt][2 * q + 1], al[mt], b[q][2], b[q][3]);
                }
#pragma unroll
            for (int q = 0; q < 4; q++)
                ldsm4t(b[q][0], b[q][1], b[q][2], b[q][3], st + 24576 + offB[1][q]);
#pragma unroll
            for (int mt = 0; mt < 2; mt++)
#pragma unroll
                for (int q = 0; q < 4; q++) {
                    mma16816(acc[mt][2 * q + 0], ah[mt], b[q][0], b[q][1]);
                    mma16816(acc[mt][2 * q + 1], ah[mt], b[q][2], b[q][3]);
                }
        }

        if (wvalid) w_sts8(i + 1, 1, f2, f3);
    }
    asm volatile("cp.async.wait_group 0;" ::: "memory");

    // epilogue: warp owns rows [wm*32, +32), cols [wn*64, +64)
    float* gp = g_part[kz];
#pragma unroll
    for (int mt = 0; mt < 2; mt++)
#pragma unroll
        for (int nf = 0; nf < 8; nf++) {
            int grow = m0 + wm * 32 + mt * 16 + (lane >> 2);
            int gcol = n0 + wn * 64 + nf * 8 + (lane & 3) * 2;
            *(float2*)&gp[(size_t)grow * Dd + gcol] =
                make_float2(acc[mt][nf][0], acc[mt][nf][1]);
            *(float2*)&gp[(size_t)(grow + 8) * Dd + gcol] =
                make_float2(acc[mt][nf][2], acc[mt][nf][3]);
        }
}

// ---------------------------------------------------------------------------
// finish: out = tanh(sum of 8 fp32 partial planes + bias)  (fixed order)
// ---------------------------------------------------------------------------
__global__ __launch_bounds__(256) void finish_kernel(
    const float* __restrict__ bias, float* __restrict__ out)
{
    int idx = blockIdx.x * 256 + threadIdx.x;        // float4 index
    int n4 = idx & (Dd / 4 - 1);
    float4 s = make_float4(0.f, 0.f, 0.f, 0.f);
#pragma unroll
    for (int p = 0; p < 8; p++) {
        float4 v = ldcs4(((const float4*)g_part[p]) + idx);
        s.x += v.x; s.y += v.y; s.z += v.z; s.w += v.w;
    }
    float4 bv = ((const float4*)bias)[n4];
    float4 r;
    r.x = tanhf(s.x + bv.x);
    r.y = tanhf(s.y + bv.y);
    r.z = tanhf(s.z + bv.z);
    r.w = tanhf(s.w + bv.w);
    ((float4*)out)[idx] = r;
}

// ---------------------------------------------------------------------------
// launch: inputs x, attribute_feat, attribute_label, W, b  (x unused: adj[A][A]=0)
// ---------------------------------------------------------------------------
extern "C" void kernel_launch(void* const* d_in, const int* in_sizes, int n_in,
                              void* d_out, int out_size) {
    (void)in_sizes; (void)n_in; (void)out_size;
    const float* feat  = (const float*)d_in[1];
    const void*  label = d_in[2];
    const float* W     = (const float*)d_in[3];
    const float* bias  = (const float*)d_in[4];
    float* out = (float*)d_out;

    cudaFuncSetAttribute(gemm_kernel, cudaFuncAttributeMaxDynamicSharedMemorySize, GEMM_SMEM);

    prep_kernel<<<AGG_BLKS, 256>>>(feat, label);
    gemm_kernel<<<dim3(Dd / 128, Bb / 128, KZ), 256, GEMM_SMEM>>>(W);
    finish_kernel<<<(Bb * Dd / 4) / 256, 256>>>(bias, out);
}